// round 12
// baseline (speedup 1.0000x reference)
#include <cuda_runtime.h>

// Problem constants (fixed by reference: B=2, S=4096, D=2)
#define S_DIM 4096
#define NB1   128      // stats blocks per batch
#define NT1   256      // stats threads per block
#define ROWS1 (S_DIM / NB1)   // 32 rows per stats block

#define CT 1024        // attn: columns per block tile (256 threads * 4)
#define RT 32          // attn: rows per block tile
#define NT2 256

// Scratch (rule: no cudaMalloc — use __device__ globals).
// Every slot is fully overwritten each launch -> deterministic, no memset needed.
__device__ double g_psum[2 * NB1];
__device__ double g_psumsq[2 * NB1];
__device__ float  g_thr[2];

// ---------------------------------------------------------------------------
// Pass 1: per-batch sum & sum-of-squares of dist_sq over the strictly-lower
// triangle (full-matrix sum = 2 * lower, diagonal contributes exactly 0).
// Rows strided by NB1 across blocks for near-perfect load balance.
// ---------------------------------------------------------------------------
__global__ void __launch_bounds__(NT1)
stats_kernel(const float* __restrict__ r)
{
    __shared__ float2 coords[S_DIM];            // 32 KB
    __shared__ double ws[NT1 / 32], wq[NT1 / 32];

    const int b = blockIdx.y;
    const float4* src4 = (const float4*)(r + (size_t)b * S_DIM * 2);
    float4* c4 = (float4*)coords;
    for (int idx = threadIdx.x; idx < S_DIM / 2; idx += NT1)
        c4[idx] = src4[idx];
    __syncthreads();

    float sum = 0.f, sumsq = 0.f;
    #pragma unroll 1
    for (int k = 0; k < ROWS1; ++k) {
        const int i = blockIdx.x + k * NB1;
        const float2 pi = coords[i];
        for (int j = threadIdx.x; j < i; j += NT1) {
            const float2 pj = coords[j];
            const float dx = pi.x - pj.x;
            const float dy = pi.y - pj.y;
            // match reference rounding: dx*dx + dy*dy, no contraction
            const float d = __fadd_rn(__fmul_rn(dx, dx), __fmul_rn(dy, dy));
            sum   = __fadd_rn(sum, d);
            sumsq = fmaf(d, d, sumsq);
        }
    }

    // deterministic tree reduction: warp shuffle (double) -> smem -> thread 0
    double s = (double)sum, q = (double)sumsq;
    #pragma unroll
    for (int o = 16; o > 0; o >>= 1) {
        s += __shfl_down_sync(0xffffffffu, s, o);
        q += __shfl_down_sync(0xffffffffu, q, o);
    }
    const int w = threadIdx.x >> 5;
    if ((threadIdx.x & 31) == 0) { ws[w] = s; wq[w] = q; }
    __syncthreads();
    if (threadIdx.x == 0) {
        double S_ = 0.0, Q_ = 0.0;
        #pragma unroll
        for (int x = 0; x < NT1 / 32; ++x) { S_ += ws[x]; Q_ += wq[x]; }
        g_psum[b * NB1 + blockIdx.x]   = S_;
        g_psumsq[b * NB1 + blockIdx.x] = Q_;
    }
}

// ---------------------------------------------------------------------------
// Pass 2: reduce the 128 partials per batch, compute
// threshold = mean + 1.25 * std (ddof=1), in double, store as float.
// Launch with 1 block of B*NB1 threads (256 for B=2): warps are batch-pure.
// ---------------------------------------------------------------------------
__global__ void finalize_kernel(int B)
{
    __shared__ double ss[8], qq[8];
    const int b = threadIdx.x / NB1;
    const int t = threadIdx.x % NB1;
    double s = 0.0, q = 0.0;
    if (b < B) { s = g_psum[b * NB1 + t]; q = g_psumsq[b * NB1 + t]; }
    #pragma unroll
    for (int o = 16; o > 0; o >>= 1) {
        s += __shfl_down_sync(0xffffffffu, s, o);
        q += __shfl_down_sync(0xffffffffu, q, o);
    }
    if ((threadIdx.x & 31) == 0) { ss[threadIdx.x >> 5] = s; qq[threadIdx.x >> 5] = q; }
    __syncthreads();
    if (t == 0 && b < B) {
        double S_ = 0.0, Q_ = 0.0;
        const int w0 = b * (NB1 / 32);
        #pragma unroll
        for (int w = 0; w < NB1 / 32; ++w) { S_ += ss[w0 + w]; Q_ += qq[w0 + w]; }
        S_ *= 2.0;  // lower triangle -> full matrix (diagonal = 0 exactly)
        Q_ *= 2.0;
        const double N = (double)S_DIM * (double)S_DIM;
        const double mean = S_ / N;
        double var = (Q_ - S_ * S_ / N) / (N - 1.0);
        if (var < 0.0) var = 0.0;
        g_thr[b] = (float)(mean + 1.25 * sqrt(var));
    }
}

// ---------------------------------------------------------------------------
// Pass 3: write the full [B,S,S] attention. Tile = RT rows x CT cols.
// Each thread owns 4 consecutive columns (float4 store per row).
// bias = 0.5*(1+cos(atan2(dy,dx))) == 0.5 + 0.5*dx*rsqrt(dist_sq); 1.0 at d==0.
// Strictly-upper float4s take a pure zero-store fast path (no MUFU/FMA).
// ---------------------------------------------------------------------------
__global__ void __launch_bounds__(NT2)
attn_kernel(const float* __restrict__ r, float* __restrict__ out)
{
    __shared__ float2 srow[RT];

    const int b  = blockIdx.z;
    const int r0 = blockIdx.y * RT;
    const int j0 = blockIdx.x * CT + threadIdx.x * 4;
    const float thr = g_thr[b];

    const float2* coords = (const float2*)(r + (size_t)b * S_DIM * 2);
    if (threadIdx.x < RT) srow[threadIdx.x] = coords[r0 + threadIdx.x];
    __syncthreads();

    // 4 column coords, held in registers across all RT rows
    const float4* c4 = (const float4*)coords;
    const float4 ca = c4[j0 >> 1];
    const float4 cb = c4[(j0 >> 1) + 1];
    const float xj[4] = {ca.x, ca.z, cb.x, cb.z};
    const float yj[4] = {ca.y, ca.w, cb.y, cb.w};

    float* base = out + ((size_t)b * S_DIM + r0) * S_DIM + j0;

    #pragma unroll 1
    for (int k = 0; k < RT; ++k) {
        const int i = r0 + k;
        float4 o;
        if (j0 > i) {
            o = make_float4(0.f, 0.f, 0.f, 0.f);   // strictly above diagonal
        } else {
            const float2 pi = srow[k];
            float v[4];
            #pragma unroll
            for (int e = 0; e < 4; ++e) {
                const float dx = pi.x - xj[e];
                const float dy = pi.y - yj[e];
                const float d  = __fadd_rn(__fmul_rn(dx, dx), __fmul_rn(dy, dy));
                // d==0 -> atan2(0,1)=0 -> bias=1 (also covers diagonal)
                const float bias = (d == 0.f) ? 1.f
                                              : fmaf(0.5f * dx, rsqrtf(d), 0.5f);
                const bool ok = (d <= thr) && ((j0 + e) <= i);
                v[e] = ok ? bias : 0.f;
            }
            o = make_float4(v[0], v[1], v[2], v[3]);
        }
        *(float4*)(base + (size_t)k * S_DIM) = o;
    }
}

// ---------------------------------------------------------------------------
extern "C" void kernel_launch(void* const* d_in, const int* in_sizes, int n_in,
                              void* d_out, int out_size)
{
    const float* r = (const float*)d_in[0];
    float* out = (float*)d_out;
    const int B = in_sizes[0] / (S_DIM * 2);   // = 2

    dim3 g1(NB1, B);
    stats_kernel<<<g1, NT1>>>(r);

    finalize_kernel<<<1, B * NB1>>>(B);

    dim3 g2(S_DIM / CT, S_DIM / RT, B);        // (4, 128, B)
    attn_kernel<<<g2, NT2>>>(r, out);
}

// round 13
// speedup vs baseline: 1.0007x; 1.0007x over previous
#include <cuda_runtime.h>

// Problem constants (fixed by reference: B=2, S=4096, D=2)
#define S_DIM 4096
#define NB1   128      // stats blocks per batch
#define NT1   256      // stats threads per block
#define ROWS1 (S_DIM / NB1)   // 32 rows per stats block

#define CT 1024        // attn: columns per block tile (256 threads * 4)
#define RT 32          // attn: rows per block tile
#define NT2 256

// Scratch (rule: no cudaMalloc — use __device__ globals).
// Every slot is fully overwritten each launch -> deterministic, no memset needed.
__device__ double g_psum[2 * NB1];
__device__ double g_psumsq[2 * NB1];
__device__ float  g_thr[2];

// ---------------------------------------------------------------------------
// Pass 1: per-batch sum & sum-of-squares of dist_sq over the strictly-lower
// triangle (full-matrix sum = 2 * lower, diagonal contributes exactly 0).
// Rows strided by NB1 across blocks for near-perfect load balance.
// ---------------------------------------------------------------------------
__global__ void __launch_bounds__(NT1)
stats_kernel(const float* __restrict__ r)
{
    __shared__ float2 coords[S_DIM];            // 32 KB
    __shared__ double ws[NT1 / 32], wq[NT1 / 32];

    const int b = blockIdx.y;
    const float4* src4 = (const float4*)(r + (size_t)b * S_DIM * 2);
    float4* c4 = (float4*)coords;
    for (int idx = threadIdx.x; idx < S_DIM / 2; idx += NT1)
        c4[idx] = src4[idx];
    __syncthreads();

    float sum = 0.f, sumsq = 0.f;
    #pragma unroll 1
    for (int k = 0; k < ROWS1; ++k) {
        const int i = blockIdx.x + k * NB1;
        const float2 pi = coords[i];
        for (int j = threadIdx.x; j < i; j += NT1) {
            const float2 pj = coords[j];
            const float dx = pi.x - pj.x;
            const float dy = pi.y - pj.y;
            // match reference rounding: dx*dx + dy*dy, no contraction
            const float d = __fadd_rn(__fmul_rn(dx, dx), __fmul_rn(dy, dy));
            sum   = __fadd_rn(sum, d);
            sumsq = fmaf(d, d, sumsq);
        }
    }

    // deterministic tree reduction: warp shuffle (double) -> smem -> thread 0
    double s = (double)sum, q = (double)sumsq;
    #pragma unroll
    for (int o = 16; o > 0; o >>= 1) {
        s += __shfl_down_sync(0xffffffffu, s, o);
        q += __shfl_down_sync(0xffffffffu, q, o);
    }
    const int w = threadIdx.x >> 5;
    if ((threadIdx.x & 31) == 0) { ws[w] = s; wq[w] = q; }
    __syncthreads();
    if (threadIdx.x == 0) {
        double S_ = 0.0, Q_ = 0.0;
        #pragma unroll
        for (int x = 0; x < NT1 / 32; ++x) { S_ += ws[x]; Q_ += wq[x]; }
        g_psum[b * NB1 + blockIdx.x]   = S_;
        g_psumsq[b * NB1 + blockIdx.x] = Q_;
    }
}

// ---------------------------------------------------------------------------
// Pass 2: reduce the 128 partials per batch, compute
// threshold = mean + 1.25 * std (ddof=1), in double, store as float.
// Launch with 1 block of B*NB1 threads (256 for B=2): warps are batch-pure.
// ---------------------------------------------------------------------------
__global__ void finalize_kernel(int B)
{
    __shared__ double ss[8], qq[8];
    const int b = threadIdx.x / NB1;
    const int t = threadIdx.x % NB1;
    double s = 0.0, q = 0.0;
    if (b < B) { s = g_psum[b * NB1 + t]; q = g_psumsq[b * NB1 + t]; }
    #pragma unroll
    for (int o = 16; o > 0; o >>= 1) {
        s += __shfl_down_sync(0xffffffffu, s, o);
        q += __shfl_down_sync(0xffffffffu, q, o);
    }
    if ((threadIdx.x & 31) == 0) { ss[threadIdx.x >> 5] = s; qq[threadIdx.x >> 5] = q; }
    __syncthreads();
    if (t == 0 && b < B) {
        double S_ = 0.0, Q_ = 0.0;
        const int w0 = b * (NB1 / 32);
        #pragma unroll
        for (int w = 0; w < NB1 / 32; ++w) { S_ += ss[w0 + w]; Q_ += qq[w0 + w]; }
        S_ *= 2.0;  // lower triangle -> full matrix (diagonal = 0 exactly)
        Q_ *= 2.0;
        const double N = (double)S_DIM * (double)S_DIM;
        const double mean = S_ / N;
        double var = (Q_ - S_ * S_ / N) / (N - 1.0);
        if (var < 0.0) var = 0.0;
        g_thr[b] = (float)(mean + 1.25 * sqrt(var));
    }
}

// ---------------------------------------------------------------------------
// Pass 3: write the full [B,S,S] attention. Tile = RT rows x CT cols.
// Each thread owns 4 consecutive columns (float4 store per row).
// bias = 0.5*(1+cos(atan2(dy,dx))) == 0.5 + 0.5*dx*rsqrt(dist_sq); 1.0 at d==0.
// Strictly-upper float4s take a pure zero-store fast path (no MUFU/FMA).
// ---------------------------------------------------------------------------
__global__ void __launch_bounds__(NT2)
attn_kernel(const float* __restrict__ r, float* __restrict__ out)
{
    __shared__ float2 srow[RT];

    const int b  = blockIdx.z;
    const int r0 = blockIdx.y * RT;
    const int j0 = blockIdx.x * CT + threadIdx.x * 4;
    const float thr = g_thr[b];

    const float2* coords = (const float2*)(r + (size_t)b * S_DIM * 2);
    if (threadIdx.x < RT) srow[threadIdx.x] = coords[r0 + threadIdx.x];
    __syncthreads();

    // 4 column coords, held in registers across all RT rows
    const float4* c4 = (const float4*)coords;
    const float4 ca = c4[j0 >> 1];
    const float4 cb = c4[(j0 >> 1) + 1];
    const float xj[4] = {ca.x, ca.z, cb.x, cb.z};
    const float yj[4] = {ca.y, ca.w, cb.y, cb.w};

    float* base = out + ((size_t)b * S_DIM + r0) * S_DIM + j0;

    #pragma unroll 1
    for (int k = 0; k < RT; ++k) {
        const int i = r0 + k;
        float4 o;
        if (j0 > i) {
            o = make_float4(0.f, 0.f, 0.f, 0.f);   // strictly above diagonal
        } else {
            const float2 pi = srow[k];
            float v[4];
            #pragma unroll
            for (int e = 0; e < 4; ++e) {
                const float dx = pi.x - xj[e];
                const float dy = pi.y - yj[e];
                const float d  = __fadd_rn(__fmul_rn(dx, dx), __fmul_rn(dy, dy));
                // d==0 -> atan2(0,1)=0 -> bias=1 (also covers diagonal)
                const float bias = (d == 0.f) ? 1.f
                                              : fmaf(0.5f * dx, rsqrtf(d), 0.5f);
                const bool ok = (d <= thr) && ((j0 + e) <= i);
                v[e] = ok ? bias : 0.f;
            }
            o = make_float4(v[0], v[1], v[2], v[3]);
        }
        *(float4*)(base + (size_t)k * S_DIM) = o;
    }
}

// ---------------------------------------------------------------------------
extern "C" void kernel_launch(void* const* d_in, const int* in_sizes, int n_in,
                              void* d_out, int out_size)
{
    const float* r = (const float*)d_in[0];
    float* out = (float*)d_out;
    const int B = in_sizes[0] / (S_DIM * 2);   // = 2

    dim3 g1(NB1, B);
    stats_kernel<<<g1, NT1>>>(r);

    finalize_kernel<<<1, B * NB1>>>(B);

    dim3 g2(S_DIM / CT, S_DIM / RT, B);        // (4, 128, B)
    attn_kernel<<<g2, NT2>>>(r, out);
}